// round 12
// baseline (speedup 1.0000x reference)
#include <cuda_runtime.h>
#include <cuda_bf16.h>
#include <cstdint>

#define U_N 100000
#define I_N 50000
#define HD  128
#define E_N 600000
#define EL_N 200000

#define NPAD 150528          // 147 * 1024  >= U_N + I_N + 1
#define NBLK 147

// ---------------- scratch (device globals: allocation-free) ----------------
__device__ float g_u1[(size_t)U_N * HD];
__device__ float g_i1[(size_t)I_N * HD];
__device__ float g_u2[(size_t)U_N * HD];
__device__ float g_i2[(size_t)I_N * HD];
__device__ int   g_cnt[NPAD];
__device__ int   g_off[NPAD];
__device__ int   g_bsum[256];
__device__ int   g_esrc_u[E_N];
__device__ int   g_esrc_i[E_N];

// ---------------- helpers ----------------------------------------------------
__device__ __forceinline__ float bfr(float x) {
    return __bfloat162float(__float2bfloat16_rn(x));
}
__device__ __forceinline__ uint32_t pkbf(float lo, float hi) {
    __nv_bfloat162 t = __floats2bfloat162_rn(lo, hi);   // (lo, hi)
    return *reinterpret_cast<uint32_t*>(&t);
}

__device__ __forceinline__ void mma_bf16(float c[4], const uint32_t a[4],
                                         const uint32_t b[2]) {
    asm volatile(
        "mma.sync.aligned.m16n8k16.row.col.f32.bf16.bf16.f32 "
        "{%0,%1,%2,%3}, {%4,%5,%6,%7}, {%8,%9}, {%0,%1,%2,%3};"
        : "+f"(c[0]), "+f"(c[1]), "+f"(c[2]), "+f"(c[3])
        : "r"(a[0]), "r"(a[1]), "r"(a[2]), "r"(a[3]), "r"(b[0]), "r"(b[1]));
}

// ---------------- CSR build --------------------------------------------------
__global__ void zero_int(int* __restrict__ p, int n) {
    int i = blockIdx.x * blockDim.x + threadIdx.x;
    int s = gridDim.x * blockDim.x;
    for (; i < n; i += s) p[i] = 0;
}

__global__ void hist_kernel(const int* __restrict__ ei, int* __restrict__ cnt) {
    int e = blockIdx.x * blockDim.x + threadIdx.x;
    if (e >= E_N) return;
    atomicAdd(cnt + ei[e], 1);
    atomicAdd(cnt + U_N + ei[E_N + e], 1);
}

__global__ void scanA(const int* __restrict__ in, int* __restrict__ out,
                      int* __restrict__ bsums) {
    __shared__ int ws[32];
    int i = blockIdx.x * 1024 + threadIdx.x;
    int lane = threadIdx.x & 31, wid = threadIdx.x >> 5;
    int v = in[i];
    int x = v;
#pragma unroll
    for (int o = 1; o < 32; o <<= 1) {
        int t = __shfl_up_sync(0xFFFFFFFFu, x, o);
        if (lane >= o) x += t;
    }
    if (lane == 31) ws[wid] = x;
    __syncthreads();
    if (wid == 0) {
        int s = ws[lane];
#pragma unroll
        for (int o = 1; o < 32; o <<= 1) {
            int t = __shfl_up_sync(0xFFFFFFFFu, s, o);
            if (lane >= o) s += t;
        }
        ws[lane] = s;
    }
    __syncthreads();
    int wpre = (wid > 0) ? ws[wid - 1] : 0;
    int incl = wpre + x;
    out[i] = incl - v;
    if (threadIdx.x == 1023) bsums[blockIdx.x] = incl;
}

__global__ void scanB(int* __restrict__ b, int nb) {
    __shared__ int ws[8];
    __shared__ int wsx[8];
    int i = threadIdx.x;
    int lane = i & 31, w = i >> 5;
    int v = (i < nb) ? b[i] : 0;
    int x = v;
#pragma unroll
    for (int o = 1; o < 32; o <<= 1) {
        int t = __shfl_up_sync(0xFFFFFFFFu, x, o);
        if (lane >= o) x += t;
    }
    if (lane == 31) ws[w] = x;
    __syncthreads();
    if (i == 0) {
        int s = 0;
        for (int k = 0; k < 8; k++) { wsx[k] = s; s += ws[k]; }
    }
    __syncthreads();
    if (i < nb) b[i] = wsx[w] + x - v;
}

__global__ void scanC(int* __restrict__ off, const int* __restrict__ b) {
    off[blockIdx.x * 1024 + threadIdx.x] += b[blockIdx.x];
}

__global__ void place_kernel(const int* __restrict__ ei, const int* __restrict__ off,
                             int* __restrict__ cur,
                             int* __restrict__ esrc_u, int* __restrict__ esrc_i) {
    int e = blockIdx.x * blockDim.x + threadIdx.x;
    if (e >= E_N) return;
    int u  = ei[e];
    int it = ei[E_N + e];
    int p = off[u] + atomicAdd(cur + u, 1);
    esrc_u[p] = it;
    int q = off[U_N + it] - E_N + atomicAdd(cur + U_N + it, 1);
    esrc_i[q] = u;
}

// ---------------- fused gather-mean + 3x bf16-split mma.sync SAGE -----------
// out[M x 128] = opt_relu( mean_csr(x_src) @ Wl + b + x_dst @ Wr )
// Phase 1: warp per dst node (16 nodes/warp), depth-4 pipelined CSR gather
//          into smem mean tile (no global agg buffer).
// Phase 2: block tile 128x128, K=256 in 8 chunks of 32; m16n8k16 bf16 split
//          hi/lo: D = Ah*Bh + Ah*Bl + Al*Bh (fp32 accumulate).
#define SM_MEAN_F (128 * 132)
#define PITCH 136
#define SM_CH (16 * PITCH)               // b32 elements per frag array
#define FUSED_SMEM ((SM_MEAN_F + 4 * SM_CH) * 4)

template <bool RELU>
__global__ __launch_bounds__(256, 2)
void sage_fused(const int* __restrict__ off, int sub, const int* __restrict__ esrc,
                const float* __restrict__ x_src, const float* __restrict__ x_dst,
                const float* __restrict__ Wl, const float* __restrict__ Wr,
                const float* __restrict__ bias, float* __restrict__ out, int M) {
    extern __shared__ float smf[];
    float* mean = smf;                               // [128][132]
    uint32_t* Ash = (uint32_t*)(smf + SM_MEAN_F);
    uint32_t* Asl = Ash + SM_CH;
    uint32_t* Bsh = Ash + 2 * SM_CH;
    uint32_t* Bsl = Ash + 3 * SM_CH;

    const int tid = threadIdx.x;
    const int lane = tid & 31;
    const int wid = tid >> 5;
    const int row0 = blockIdx.x * 128;

    // ---- phase 1: CSR mean gather, depth-4 pipeline ----
#pragma unroll 1
    for (int t = 0; t < 16; t++) {
        int local = wid * 16 + t;
        int gnode = row0 + local;
        float4 acc = make_float4(0.f, 0.f, 0.f, 0.f);
        float sc = 0.f;
        if (gnode < M) {
            int estart = off[gnode] - sub;
            int deg = off[gnode + 1] - off[gnode];
#pragma unroll 1
            for (int j = 0; j < deg; j += 32) {
                int sid = (j + lane < deg) ? esrc[estart + j + lane] : 0;
                int lim = min(32, deg - j);
                float4 b0, b1, b2, b3;
                int s;
                s = __shfl_sync(0xFFFFFFFFu, sid, 0);
                b0 = ((const float4*)(x_src + (size_t)s * HD))[lane];
                if (1 < lim) { s = __shfl_sync(0xFFFFFFFFu, sid, 1);
                               b1 = ((const float4*)(x_src + (size_t)s * HD))[lane]; }
                if (2 < lim) { s = __shfl_sync(0xFFFFFFFFu, sid, 2);
                               b2 = ((const float4*)(x_src + (size_t)s * HD))[lane]; }
                if (3 < lim) { s = __shfl_sync(0xFFFFFFFFu, sid, 3);
                               b3 = ((const float4*)(x_src + (size_t)s * HD))[lane]; }
#pragma unroll 1
                for (int jj = 0; jj < lim; jj += 4) {
                    acc.x += b0.x; acc.y += b0.y; acc.z += b0.z; acc.w += b0.w;
                    if (jj + 4 < lim) {
                        s = __shfl_sync(0xFFFFFFFFu, sid, jj + 4);
                        b0 = ((const float4*)(x_src + (size_t)s * HD))[lane];
                    }
                    if (jj + 1 < lim) {
                        acc.x += b1.x; acc.y += b1.y; acc.z += b1.z; acc.w += b1.w;
                        if (jj + 5 < lim) {
                            s = __shfl_sync(0xFFFFFFFFu, sid, jj + 5);
                            b1 = ((const float4*)(x_src + (size_t)s * HD))[lane];
                        }
                    }
                    if (jj + 2 < lim) {
                        acc.x += b2.x; acc.y += b2.y; acc.z += b2.z; acc.w += b2.w;
                        if (jj + 6 < lim) {
                            s = __shfl_sync(0xFFFFFFFFu, sid, jj + 6);
                            b2 = ((const float4*)(x_src + (size_t)s * HD))[lane];
                        }
                    }
                    if (jj + 3 < lim) {
                        acc.x += b3.x; acc.y += b3.y; acc.z += b3.z; acc.w += b3.w;
                        if (jj + 7 < lim) {
                            s = __shfl_sync(0xFFFFFFFFu, sid, jj + 7);
                            b3 = ((const float4*)(x_src + (size_t)s * HD))[lane];
                        }
                    }
                }
            }
            sc = 1.0f / fmaxf((float)deg, 1.0f);
        }
        float4 m = make_float4(acc.x * sc, acc.y * sc, acc.z * sc, acc.w * sc);
        *(float4*)&mean[local * 132 + lane * 4] = m;
    }
    __syncthreads();

    // ---- phase 2: GEMM ----
    const int wm = wid & 3;
    const int wn = wid >> 2;
    const int g = lane >> 2;          // 0..7
    const int tig = lane & 3;         // 0..3

    float c[2][8][4];
#pragma unroll
    for (int mt = 0; mt < 2; mt++)
#pragma unroll
        for (int nt = 0; nt < 8; nt++)
#pragma unroll
            for (int q = 0; q < 4; q++) c[mt][nt][q] = 0.f;

#pragma unroll 1
    for (int kt = 0; kt < 8; kt++) {
        const bool isAgg = kt < 4;
        const int kbase = (kt & 3) * 32;
        const float* __restrict__ W = isAgg ? Wl : Wr;

        // A chunk: 128 rows x 32 k -> [kk2 0..15][row] bf16x2, hi and lo
#pragma unroll
        for (int rep = 0; rep < 4; rep++) {
            int fid = tid + rep * 256;     // 0..1023
            int r = fid >> 3;              // 0..127
            int c4 = fid & 7;              // float4 (4 k) index
            float4 v;
            if (isAgg) {
                v = *(const float4*)&mean[r * 132 + kbase + c4 * 4];
            } else {
                int grow = row0 + r;
                v = make_float4(0.f, 0.f, 0.f, 0.f);
                if (grow < M)
                    v = ((const float4*)(x_dst + (size_t)grow * HD + kbase))[c4];
            }
            float hx = bfr(v.x), hy = bfr(v.y), hz = bfr(v.z), hw = bfr(v.w);
            Ash[(c4 * 2 + 0) * PITCH + r] = pkbf(hx, hy);
            Ash[(c4 * 2 + 1) * PITCH + r] = pkbf(hz, hw);
            Asl[(c4 * 2 + 0) * PITCH + r] = pkbf(v.x - hx, v.y - hy);
            Asl[(c4 * 2 + 1) * PITCH + r] = pkbf(v.z - hz, v.w - hw);
        }
        // B chunk: 32 k x 128 n -> [kk2][n] bf16x2 pairs over (k, k+1)
#pragma unroll
        for (int rep = 0; rep < 2; rep++) {
            int fid = tid + rep * 256;     // 0..511
            int kk2 = fid >> 5;            // 0..15
            int n4 = fid & 31;             // 0..31 (group of 4 n)
            const float* w0 = W + (size_t)(kbase + kk2 * 2) * HD + n4 * 4;
            float4 v0 = *(const float4*)w0;
            float4 v1 = *(const float4*)(w0 + HD);
            float h0x = bfr(v0.x), h0y = bfr(v0.y), h0z = bfr(v0.z), h0w = bfr(v0.w);
            float h1x = bfr(v1.x), h1y = bfr(v1.y), h1z = bfr(v1.z), h1w = bfr(v1.w);
            uint4 hv = make_uint4(pkbf(h0x, h1x), pkbf(h0y, h1y),
                                  pkbf(h0z, h1z), pkbf(h0w, h1w));
            uint4 lv = make_uint4(pkbf(v0.x - h0x, v1.x - h1x),
                                  pkbf(v0.y - h0y, v1.y - h1y),
                                  pkbf(v0.z - h0z, v1.z - h1z),
                                  pkbf(v0.w - h0w, v1.w - h1w));
            *(uint4*)&Bsh[kk2 * PITCH + n4 * 4] = hv;
            *(uint4*)&Bsl[kk2 * PITCH + n4 * 4] = lv;
        }
        __syncthreads();

#pragma unroll
        for (int ks = 0; ks < 2; ks++) {
            const int arow = ks * 8;       // kk2 base for this k16 step
            uint32_t ah[2][4], al[2][4];
#pragma unroll
            for (int mt = 0; mt < 2; mt++) {
                int m0 = wm * 32 + mt * 16;
                ah[mt][0] = Ash[(arow + tig) * PITCH + m0 + g];
                ah[mt][1] = Ash[(arow + tig) * PITCH + m0 + g + 8];
                ah[mt][2] = Ash[(arow + tig + 4) * PITCH + m0 + g];
                ah[mt][3] = Ash[(arow + tig + 4) * PITCH + m0 + g + 8];
                al[mt][0] = Asl[(arow + tig) * PITCH + m0 + g];
                al[mt][1] = Asl[(arow + tig) * PITCH + m0 + g + 8];
                al[mt][2] = Asl[(arow + tig + 4) * PITCH + m0 + g];
                al[mt][3] = Asl[(arow + tig + 4) * PITCH + m0 + g + 8];
            }
#pragma unroll
            for (int nt = 0; nt < 8; nt++) {
                int n0 = wn * 64 + nt * 8;
                uint32_t bh[2], bl[2];
                bh[0] = Bsh[(arow + tig) * PITCH + n0 + g];
                bh[1] = Bsh[(arow + tig + 4) * PITCH + n0 + g];
                bl[0] = Bsl[(arow + tig) * PITCH + n0 + g];
                bl[1] = Bsl[(arow + tig + 4) * PITCH + n0 + g];
                mma_bf16(c[0][nt], ah[0], bh);
                mma_bf16(c[1][nt], ah[1], bh);
                mma_bf16(c[0][nt], ah[0], bl);
                mma_bf16(c[1][nt], ah[1], bl);
                mma_bf16(c[0][nt], al[0], bh);
                mma_bf16(c[1][nt], al[1], bh);
            }
        }
        __syncthreads();
    }

    // epilogue: c0,c1 -> row g cols col,col+1 ; c2,c3 -> row g+8
#pragma unroll
    for (int mt = 0; mt < 2; mt++) {
        int r_lo = row0 + wm * 32 + mt * 16 + g;
        int r_hi = r_lo + 8;
#pragma unroll
        for (int nt = 0; nt < 8; nt++) {
            int col = wn * 64 + nt * 8 + tig * 2;
            float b0 = bias[col], b1 = bias[col + 1];
            float v0 = c[mt][nt][0] + b0;
            float v1 = c[mt][nt][1] + b1;
            float v2 = c[mt][nt][2] + b0;
            float v3 = c[mt][nt][3] + b1;
            if (RELU) {
                v0 = fmaxf(v0, 0.f); v1 = fmaxf(v1, 0.f);
                v2 = fmaxf(v2, 0.f); v3 = fmaxf(v3, 0.f);
            }
            if (r_lo < M) {
                float2 o = make_float2(v0, v1);
                *(float2*)(out + (size_t)r_lo * HD + col) = o;
            }
            if (r_hi < M) {
                float2 o = make_float2(v2, v3);
                *(float2*)(out + (size_t)r_hi * HD + col) = o;
            }
        }
    }
}

// ---------------- edge dot-product classifier ------------------------------
__global__ void classify_kernel(const float* __restrict__ u2, const float* __restrict__ i2,
                                const int* __restrict__ lbl, float* __restrict__ out) {
    int e = blockIdx.x * (blockDim.x >> 5) + (threadIdx.x >> 5);
    if (e >= EL_N) return;
    int lane = threadIdx.x & 31;
    int u  = lbl[e];
    int it = lbl[EL_N + e];
    float4 a = ((const float4*)(u2 + (size_t)u * HD))[lane];
    float4 b = ((const float4*)(i2 + (size_t)it * HD))[lane];
    float s = a.x * b.x + a.y * b.y + a.z * b.z + a.w * b.w;
#pragma unroll
    for (int o = 16; o > 0; o >>= 1) s += __shfl_xor_sync(0xFFFFFFFFu, s, o);
    if (lane == 0) out[e] = s;
}

// ---------------- launch ----------------------------------------------------
extern "C" void kernel_launch(void* const* d_in, const int* in_sizes, int n_in,
                              void* d_out, int out_size) {
    const float* user_emb = (const float*)d_in[0];
    const float* item_emb = (const float*)d_in[1];
    const float* w1_ui_l = (const float*)d_in[2];
    const float* w1_ui_r = (const float*)d_in[3];
    const float* w1_iu_l = (const float*)d_in[4];
    const float* w1_iu_r = (const float*)d_in[5];
    const float* w2_ui_l = (const float*)d_in[6];
    const float* w2_ui_r = (const float*)d_in[7];
    const float* w2_iu_l = (const float*)d_in[8];
    const float* w2_iu_r = (const float*)d_in[9];
    const float* b1_ui = (const float*)d_in[10];
    const float* b1_iu = (const float*)d_in[11];
    const float* b2_ui = (const float*)d_in[12];
    const float* b2_iu = (const float*)d_in[13];
    const int* ei_ui = (const int*)d_in[16];
    const int* lbl   = (const int*)d_in[18];
    float* out = (float*)d_out;

    float *u1, *i1, *u2, *i2;
    int *cnt, *off, *bsum, *esrc_u, *esrc_i;
    cudaGetSymbolAddress((void**)&u1, g_u1);
    cudaGetSymbolAddress((void**)&i1, g_i1);
    cudaGetSymbolAddress((void**)&u2, g_u2);
    cudaGetSymbolAddress((void**)&i2, g_i2);
    cudaGetSymbolAddress((void**)&cnt, g_cnt);
    cudaGetSymbolAddress((void**)&off, g_off);
    cudaGetSymbolAddress((void**)&bsum, g_bsum);
    cudaGetSymbolAddress((void**)&esrc_u, g_esrc_u);
    cudaGetSymbolAddress((void**)&esrc_i, g_esrc_i);

    cudaFuncSetAttribute(sage_fused<true>,
                         cudaFuncAttributeMaxDynamicSharedMemorySize, FUSED_SMEM);
    cudaFuncSetAttribute(sage_fused<false>,
                         cudaFuncAttributeMaxDynamicSharedMemorySize, FUSED_SMEM);

    // ---- CSR build (shared by both layers) ----
    zero_int<<<147, 1024>>>(cnt, NPAD);
    hist_kernel<<<(E_N + 255) / 256, 256>>>(ei_ui, cnt);
    scanA<<<NBLK, 1024>>>(cnt, off, bsum);
    scanB<<<1, 256>>>(bsum, NBLK);
    scanC<<<NBLK, 1024>>>(off, bsum);
    zero_int<<<147, 1024>>>(cnt, NPAD);
    place_kernel<<<(E_N + 255) / 256, 256>>>(ei_ui, off, cnt, esrc_u, esrc_i);

    const int UB = (U_N + 127) / 128;
    const int IB = (I_N + 127) / 128;

    // ---- layer 1 ----
    sage_fused<true><<<UB, 256, FUSED_SMEM>>>(off, 0, esrc_u,
        item_emb, user_emb, w1_iu_l, w1_iu_r, b1_iu, u1, U_N);
    sage_fused<true><<<IB, 256, FUSED_SMEM>>>(off + U_N, E_N, esrc_i,
        user_emb, item_emb, w1_ui_l, w1_ui_r, b1_ui, i1, I_N);

    // ---- layer 2 ----
    sage_fused<false><<<UB, 256, FUSED_SMEM>>>(off, 0, esrc_u,
        i1, u1, w2_iu_l, w2_iu_r, b2_iu, u2, U_N);
    sage_fused<false><<<IB, 256, FUSED_SMEM>>>(off + U_N, E_N, esrc_i,
        u1, i1, w2_ui_l, w2_ui_r, b2_ui, i2, I_N);

    // ---- classifier ----
    classify_kernel<<<(EL_N + 7) / 8, 256>>>(u2, i2, lbl, out);
}

// round 13
// speedup vs baseline: 1.4450x; 1.4450x over previous
#include <cuda_runtime.h>
#include <cuda_bf16.h>
#include <cstdint>

#define U_N 100000
#define I_N 50000
#define N_TOT (U_N + I_N)
#define HD  128
#define E_N 600000
#define EL_N 200000

#define NPAD 150528          // 147 * 1024  >= U_N + I_N + 1
#define NBLK 147

// ---------------- scratch (device globals: allocation-free) ----------------
__device__ float g_u1[(size_t)U_N * HD];
__device__ float g_i1[(size_t)I_N * HD];
__device__ float g_u2[(size_t)U_N * HD];
__device__ float g_i2[(size_t)I_N * HD];
__device__ float g_mean[(size_t)N_TOT * HD];   // u means at 0, i means at U_N*HD
__device__ int   g_cnt[NPAD];
__device__ int   g_cur[NPAD];
__device__ int   g_off[NPAD];
__device__ int   g_bsum[256];
__device__ int   g_esrc_u[E_N];
__device__ int   g_esrc_i[E_N];

// ---------------- helpers ----------------------------------------------------
__device__ __forceinline__ float bfr(float x) {
    return __bfloat162float(__float2bfloat16_rn(x));
}
__device__ __forceinline__ uint32_t pkbf(float lo, float hi) {
    __nv_bfloat162 t = __floats2bfloat162_rn(lo, hi);   // (lo, hi)
    return *reinterpret_cast<uint32_t*>(&t);
}
__device__ __forceinline__ void mma_bf16(float c[4], const uint32_t a[4],
                                         const uint32_t b[2]) {
    asm volatile(
        "mma.sync.aligned.m16n8k16.row.col.f32.bf16.bf16.f32 "
        "{%0,%1,%2,%3}, {%4,%5,%6,%7}, {%8,%9}, {%0,%1,%2,%3};"
        : "+f"(c[0]), "+f"(c[1]), "+f"(c[2]), "+f"(c[3])
        : "r"(a[0]), "r"(a[1]), "r"(a[2]), "r"(a[3]), "r"(b[0]), "r"(b[1]));
}
// final CSR offset: block-local exclusive scan + block prefix
__device__ __forceinline__ int Ofin(const int* __restrict__ off,
                                    const int* __restrict__ bsum, int x) {
    return off[x] + bsum[x >> 10];
}

// ---------------- CSR build (5 launches) ------------------------------------
__global__ void zero2_int(int* __restrict__ a, int* __restrict__ b, int n) {
    int i = blockIdx.x * blockDim.x + threadIdx.x;
    int s = gridDim.x * blockDim.x;
    for (; i < n; i += s) { a[i] = 0; b[i] = 0; }
}

__global__ void hist_kernel(const int* __restrict__ ei, int* __restrict__ cnt) {
    int e = blockIdx.x * blockDim.x + threadIdx.x;
    if (e >= E_N) return;
    atomicAdd(cnt + ei[e], 1);
    atomicAdd(cnt + U_N + ei[E_N + e], 1);
}

__global__ void scanA(const int* __restrict__ in, int* __restrict__ out,
                      int* __restrict__ bsums) {
    __shared__ int ws[32];
    int i = blockIdx.x * 1024 + threadIdx.x;
    int lane = threadIdx.x & 31, wid = threadIdx.x >> 5;
    int v = in[i];
    int x = v;
#pragma unroll
    for (int o = 1; o < 32; o <<= 1) {
        int t = __shfl_up_sync(0xFFFFFFFFu, x, o);
        if (lane >= o) x += t;
    }
    if (lane == 31) ws[wid] = x;
    __syncthreads();
    if (wid == 0) {
        int s = ws[lane];
#pragma unroll
        for (int o = 1; o < 32; o <<= 1) {
            int t = __shfl_up_sync(0xFFFFFFFFu, s, o);
            if (lane >= o) s += t;
        }
        ws[lane] = s;
    }
    __syncthreads();
    int wpre = (wid > 0) ? ws[wid - 1] : 0;
    int incl = wpre + x;
    out[i] = incl - v;
    if (threadIdx.x == 1023) bsums[blockIdx.x] = incl;
}

__global__ void scanB(int* __restrict__ b, int nb) {
    __shared__ int ws[8];
    __shared__ int wsx[8];
    int i = threadIdx.x;
    int lane = i & 31, w = i >> 5;
    int v = (i < nb) ? b[i] : 0;
    int x = v;
#pragma unroll
    for (int o = 1; o < 32; o <<= 1) {
        int t = __shfl_up_sync(0xFFFFFFFFu, x, o);
        if (lane >= o) x += t;
    }
    if (lane == 31) ws[w] = x;
    __syncthreads();
    if (i == 0) {
        int s = 0;
        for (int k = 0; k < 8; k++) { wsx[k] = s; s += ws[k]; }
    }
    __syncthreads();
    if (i < nb) b[i] = wsx[w] + x - v;
}

__global__ void place_kernel(const int* __restrict__ ei, const int* __restrict__ off,
                             const int* __restrict__ bsum, int* __restrict__ cur,
                             int* __restrict__ esrc_u, int* __restrict__ esrc_i) {
    int e = blockIdx.x * blockDim.x + threadIdx.x;
    if (e >= E_N) return;
    int u  = ei[e];
    int it = ei[E_N + e];
    int p = Ofin(off, bsum, u) + atomicAdd(cur + u, 1);
    esrc_u[p] = it;
    int q = Ofin(off, bsum, U_N + it) - E_N + atomicAdd(cur + U_N + it, 1);
    esrc_i[q] = u;
}

// ---------------- merged CSR mean gather (warp/node, depth-4 pipeline) ------
// Covers both partitions in one launch: nodes [0,U_N) gather from xs_u,
// nodes [U_N,N_TOT) gather from xs_i. Output rows contiguous in g_mean.
__global__ void mean_all(const int* __restrict__ off, const int* __restrict__ bsum,
                         const int* __restrict__ esrc_u, const int* __restrict__ esrc_i,
                         const float* __restrict__ xs_u, const float* __restrict__ xs_i,
                         float* __restrict__ mean_out) {
    int node = blockIdx.x * 8 + (threadIdx.x >> 5);
    if (node >= N_TOT) return;
    int lane = threadIdx.x & 31;
    const bool isU = node < U_N;
    const float* __restrict__ x_src = isU ? xs_u : xs_i;
    const int* __restrict__ esrc = isU ? esrc_u : esrc_i;
    int o0 = Ofin(off, bsum, node);
    int deg = Ofin(off, bsum, node + 1) - o0;
    int estart = isU ? o0 : (o0 - E_N);

    float4 acc = make_float4(0.f, 0.f, 0.f, 0.f);
#pragma unroll 1
    for (int j = 0; j < deg; j += 32) {
        int sid = (j + lane < deg) ? esrc[estart + j + lane] : 0;
        int lim = min(32, deg - j);
        float4 b0, b1, b2, b3;
        int s;
        s = __shfl_sync(0xFFFFFFFFu, sid, 0);
        b0 = ((const float4*)(x_src + (size_t)s * HD))[lane];
        if (1 < lim) { s = __shfl_sync(0xFFFFFFFFu, sid, 1);
                       b1 = ((const float4*)(x_src + (size_t)s * HD))[lane]; }
        if (2 < lim) { s = __shfl_sync(0xFFFFFFFFu, sid, 2);
                       b2 = ((const float4*)(x_src + (size_t)s * HD))[lane]; }
        if (3 < lim) { s = __shfl_sync(0xFFFFFFFFu, sid, 3);
                       b3 = ((const float4*)(x_src + (size_t)s * HD))[lane]; }
#pragma unroll 1
        for (int jj = 0; jj < lim; jj += 4) {
            acc.x += b0.x; acc.y += b0.y; acc.z += b0.z; acc.w += b0.w;
            if (jj + 4 < lim) {
                s = __shfl_sync(0xFFFFFFFFu, sid, jj + 4);
                b0 = ((const float4*)(x_src + (size_t)s * HD))[lane];
            }
            if (jj + 1 < lim) {
                acc.x += b1.x; acc.y += b1.y; acc.z += b1.z; acc.w += b1.w;
                if (jj + 5 < lim) {
                    s = __shfl_sync(0xFFFFFFFFu, sid, jj + 5);
                    b1 = ((const float4*)(x_src + (size_t)s * HD))[lane];
                }
            }
            if (jj + 2 < lim) {
                acc.x += b2.x; acc.y += b2.y; acc.z += b2.z; acc.w += b2.w;
                if (jj + 6 < lim) {
                    s = __shfl_sync(0xFFFFFFFFu, sid, jj + 6);
                    b2 = ((const float4*)(x_src + (size_t)s * HD))[lane];
                }
            }
            if (jj + 3 < lim) {
                acc.x += b3.x; acc.y += b3.y; acc.z += b3.z; acc.w += b3.w;
                if (jj + 7 < lim) {
                    s = __shfl_sync(0xFFFFFFFFu, sid, jj + 7);
                    b3 = ((const float4*)(x_src + (size_t)s * HD))[lane];
                }
            }
        }
    }
    float sc = 1.0f / fmaxf((float)deg, 1.0f);
    float4 m = make_float4(acc.x * sc, acc.y * sc, acc.z * sc, acc.w * sc);
    ((float4*)(mean_out + (size_t)node * HD))[lane] = m;
}

// ---------------- merged 3x bf16-split mma.sync SAGE GEMM -------------------
// One launch covers both partitions: blocks [0,UB) do the u side, [UB,UB+IB)
// the i side. out[Mx128] = opt_relu(mean @ Wl + b + x_dst @ Wr), K=256 in 8
// chunks of 32; m16n8k16 bf16 split hi/lo: D = Ah*Bh + Ah*Bl + Al*Bh.
#define PITCH 136
#define SM_CH (16 * PITCH)               // b32 elements per frag array
#define GEMM_SMEM (4 * SM_CH * 4)
#define UB ((U_N + 127) / 128)
#define IB ((I_N + 127) / 128)

template <bool RELU>
__global__ __launch_bounds__(256, 2)
void sage_gemm_mma(const float* __restrict__ mean_all_buf,
                   const float* __restrict__ xd_u, const float* __restrict__ xd_i,
                   const float* __restrict__ Wl_u, const float* __restrict__ Wr_u,
                   const float* __restrict__ Wl_i, const float* __restrict__ Wr_i,
                   const float* __restrict__ bias_u, const float* __restrict__ bias_i,
                   float* __restrict__ out_u, float* __restrict__ out_i) {
    extern __shared__ uint32_t sm[];
    uint32_t* Ash = sm;
    uint32_t* Asl = sm + SM_CH;
    uint32_t* Bsh = sm + 2 * SM_CH;
    uint32_t* Bsl = sm + 3 * SM_CH;

    const bool isU = blockIdx.x < UB;
    const int bid = isU ? blockIdx.x : (blockIdx.x - UB);
    const int M = isU ? U_N : I_N;
    const float* __restrict__ meanA = mean_all_buf + (isU ? 0 : (size_t)U_N * HD);
    const float* __restrict__ x_dst = isU ? xd_u : xd_i;
    const float* __restrict__ WlP = isU ? Wl_u : Wl_i;
    const float* __restrict__ WrP = isU ? Wr_u : Wr_i;
    const float* __restrict__ bias = isU ? bias_u : bias_i;
    float* __restrict__ out = isU ? out_u : out_i;

    const int tid = threadIdx.x;
    const int lane = tid & 31;
    const int wid = tid >> 5;
    const int wm = wid & 3;
    const int wn = wid >> 2;
    const int row0 = bid * 128;
    const int g = lane >> 2;          // 0..7
    const int tig = lane & 3;         // 0..3

    float c[2][8][4];
#pragma unroll
    for (int mt = 0; mt < 2; mt++)
#pragma unroll
        for (int nt = 0; nt < 8; nt++)
#pragma unroll
            for (int q = 0; q < 4; q++) c[mt][nt][q] = 0.f;

#pragma unroll 1
    for (int kt = 0; kt < 8; kt++) {
        const bool isAgg = kt < 4;
        const int kbase = (kt & 3) * 32;
        const float* __restrict__ A = isAgg ? meanA : x_dst;
        const float* __restrict__ W = isAgg ? WlP : WrP;

        // A chunk: 128 rows x 32 k -> [kk2 0..15][row] bf16x2, hi and lo
#pragma unroll
        for (int rep = 0; rep < 4; rep++) {
            int fid = tid + rep * 256;     // 0..1023
            int r = fid >> 3;              // 0..127
            int c4 = fid & 7;              // float4 (4 k) index
            int grow = row0 + r;
            float4 v = make_float4(0.f, 0.f, 0.f, 0.f);
            if (grow < M)
                v = ((const float4*)(A + (size_t)grow * HD + kbase))[c4];
            float hx = bfr(v.x), hy = bfr(v.y), hz = bfr(v.z), hw = bfr(v.w);
            Ash[(c4 * 2 + 0) * PITCH + r] = pkbf(hx, hy);
            Ash[(c4 * 2 + 1) * PITCH + r] = pkbf(hz, hw);
            Asl[(c4 * 2 + 0) * PITCH + r] = pkbf(v.x - hx, v.y - hy);
            Asl[(c4 * 2 + 1) * PITCH + r] = pkbf(v.z - hz, v.w - hw);
        }
        // B chunk: 32 k x 128 n -> [kk2][n] bf16x2 pairs over (k, k+1)
#pragma unroll
        for (int rep = 0; rep < 2; rep++) {
            int fid = tid + rep * 256;     // 0..511
            int kk2 = fid >> 5;            // 0..15
            int n4 = fid & 31;             // 0..31 (group of 4 n)
            const float* w0 = W + (size_t)(kbase + kk2 * 2) * HD + n4 * 4;
            float4 v0 = *(const float4*)w0;
            float4 v1 = *(const float4*)(w0 + HD);
            float h0x = bfr(v0.x), h0y = bfr(v0.y), h0z = bfr(v0.z), h0w = bfr(v0.w);
            float h1x = bfr(v1.x), h1y = bfr(v1.y), h1z = bfr(v1.z), h1w = bfr(v1.w);
            uint4 hv = make_uint4(pkbf(h0x, h1x), pkbf(h0y, h1y),
                                  pkbf(h0z, h1z), pkbf(h0w, h1w));
            uint4 lv = make_uint4(pkbf(v0.x - h0x, v1.x - h1x),
                                  pkbf(v0.y - h0y, v1.y - h1y),
                                  pkbf(v0.z - h0z, v1.z - h1z),
                                  pkbf(v0.w - h0w, v1.w - h1w));
            *(uint4*)&Bsh[kk2 * PITCH + n4 * 4] = hv;
            *(uint4*)&Bsl[kk2 * PITCH + n4 * 4] = lv;
        }
        __syncthreads();

#pragma unroll
        for (int ks = 0; ks < 2; ks++) {
            const int arow = ks * 8;       // kk2 base for this k16 step
            uint32_t ah[2][4], al[2][4];
#pragma unroll
            for (int mt = 0; mt < 2; mt++) {
                int m0 = wm * 32 + mt * 16;
                ah[mt][0] = Ash[(arow + tig) * PITCH + m0 + g];
                ah[mt][1] = Ash[(arow + tig) * PITCH + m0 + g + 8];
                ah[mt][2] = Ash[(arow + tig + 4) * PITCH + m0 + g];
                ah[mt][3] = Ash[(arow + tig + 4) * PITCH + m0 + g + 8];
                al[mt][0] = Asl[(arow + tig) * PITCH + m0 + g];
                al[mt][1] = Asl[(arow + tig) * PITCH + m0 + g + 8];
                al[mt][2] = Asl[(arow + tig + 4) * PITCH + m0 + g];
                al[mt][3] = Asl[(arow + tig + 4) * PITCH + m0 + g + 8];
            }
#pragma unroll
            for (int nt = 0; nt < 8; nt++) {
                int n0 = wn * 64 + nt * 8;
                uint32_t bh[2], bl[2];
                bh[0] = Bsh[(arow + tig) * PITCH + n0 + g];
                bh[1] = Bsh[(arow + tig + 4) * PITCH + n0 + g];
                bl[0] = Bsl[(arow + tig) * PITCH + n0 + g];
                bl[1] = Bsl[(arow + tig + 4) * PITCH + n0 + g];
                mma_bf16(c[0][nt], ah[0], bh);
                mma_bf16(c[1][nt], ah[1], bh);
                mma_bf16(c[0][nt], ah[0], bl);
                mma_bf16(c[1][nt], ah[1], bl);
                mma_bf16(c[0][nt], al[0], bh);
                mma_bf16(c[1][nt], al[1], bh);
            }
        }
        __syncthreads();
    }

    // epilogue
#pragma unroll
    for (int mt = 0; mt < 2; mt++) {
        int r_lo = row0 + wm * 32 + mt * 16 + g;
        int r_hi = r_lo + 8;
#pragma unroll
        for (int nt = 0; nt < 8; nt++) {
            int col = wn * 64 + nt * 8 + tig * 2;
            float b0 = bias[col], b1 = bias[col + 1];
            float v0 = c[mt][nt][0] + b0;
            float v1 = c[mt][nt][1] + b1;
            float v2 = c[mt][nt][2] + b0;
            float v3 = c[mt][nt][3] + b1;
            if (RELU) {
                v0 = fmaxf(v0, 0.f); v1 = fmaxf(v1, 0.f);
                v2 = fmaxf(v2, 0.f); v3 = fmaxf(v3, 0.f);
            }
            if (r_lo < M) {
                float2 o = make_float2(v0, v1);
                *(float2*)(out + (size_t)r_lo * HD + col) = o;
            }
            if (r_hi < M) {
                float2 o = make_float2(v2, v3);
                *(float2*)(out + (size_t)r_hi * HD + col) = o;
            }
        }
    }
}

// ---------------- edge dot-product classifier ------------------------------
__global__ void classify_kernel(const float* __restrict__ u2, const float* __restrict__ i2,
                                const int* __restrict__ lbl, float* __restrict__ out) {
    int e = blockIdx.x * (blockDim.x >> 5) + (threadIdx.x >> 5);
    if (e >= EL_N) return;
    int lane = threadIdx.x & 31;
    int u  = lbl[e];
    int it = lbl[EL_N + e];
    float4 a = ((const float4*)(u2 + (size_t)u * HD))[lane];
    float4 b = ((const float4*)(i2 + (size_t)it * HD))[lane];
    float s = a.x * b.x + a.y * b.y + a.z * b.z + a.w * b.w;
#pragma unroll
    for (int o = 16; o > 0; o >>= 1) s += __shfl_xor_sync(0xFFFFFFFFu, s, o);
    if (lane == 0) out[e] = s;
}

// ---------------- launch ----------------------------------------------------
extern "C" void kernel_launch(void* const* d_in, const int* in_sizes, int n_in,
                              void* d_out, int out_size) {
    const float* user_emb = (const float*)d_in[0];
    const float* item_emb = (const float*)d_in[1];
    const float* w1_ui_l = (const float*)d_in[2];
    const float* w1_ui_r = (const float*)d_in[3];
    const float* w1_iu_l = (const float*)d_in[4];
    const float* w1_iu_r = (const float*)d_in[5];
    const float* w2_ui_l = (const float*)d_in[6];
    const float* w2_ui_r = (const float*)d_in[7];
    const float* w2_iu_l = (const float*)d_in[8];
    const float* w2_iu_r = (const float*)d_in[9];
    const float* b1_ui = (const float*)d_in[10];
    const float* b1_iu = (const float*)d_in[11];
    const float* b2_ui = (const float*)d_in[12];
    const float* b2_iu = (const float*)d_in[13];
    const int* ei_ui = (const int*)d_in[16];
    const int* lbl   = (const int*)d_in[18];
    float* out = (float*)d_out;

    float *u1, *i1, *u2, *i2, *meanb;
    int *cnt, *cur, *off, *bsum, *esrc_u, *esrc_i;
    cudaGetSymbolAddress((void**)&u1, g_u1);
    cudaGetSymbolAddress((void**)&i1, g_i1);
    cudaGetSymbolAddress((void**)&u2, g_u2);
    cudaGetSymbolAddress((void**)&i2, g_i2);
    cudaGetSymbolAddress((void**)&meanb, g_mean);
    cudaGetSymbolAddress((void**)&cnt, g_cnt);
    cudaGetSymbolAddress((void**)&cur, g_cur);
    cudaGetSymbolAddress((void**)&off, g_off);
    cudaGetSymbolAddress((void**)&bsum, g_bsum);
    cudaGetSymbolAddress((void**)&esrc_u, g_esrc_u);
    cudaGetSymbolAddress((void**)&esrc_i, g_esrc_i);

    cudaFuncSetAttribute(sage_gemm_mma<true>,
                         cudaFuncAttributeMaxDynamicSharedMemorySize, GEMM_SMEM);
    cudaFuncSetAttribute(sage_gemm_mma<false>,
                         cudaFuncAttributeMaxDynamicSharedMemorySize, GEMM_SMEM);

    // ---- CSR build: 5 launches (scanC folded into consumers via bsum) ----
    zero2_int<<<147, 1024>>>(cnt, cur, NPAD);                       // 1
    hist_kernel<<<(E_N + 255) / 256, 256>>>(ei_ui, cnt);            // 2
    scanA<<<NBLK, 1024>>>(cnt, off, bsum);                          // 3
    scanB<<<1, 256>>>(bsum, NBLK);                                  // 4
    place_kernel<<<(E_N + 255) / 256, 256>>>(ei_ui, off, bsum, cur,
                                             esrc_u, esrc_i);       // 5

    const int MB = (N_TOT + 7) / 8;

    // ---- layer 1 ----
    mean_all<<<MB, 256>>>(off, bsum, esrc_u, esrc_i,
                          item_emb, user_emb, meanb);               // 6 (profiled)
    sage_gemm_mma<true><<<UB + IB, 256, GEMM_SMEM>>>(meanb,
        user_emb, item_emb,
        w1_iu_l, w1_iu_r, w1_ui_l, w1_ui_r,
        b1_iu, b1_ui, u1, i1);                                      // 7

    // ---- layer 2 ----
    mean_all<<<MB, 256>>>(off, bsum, esrc_u, esrc_i,
                          i1, u1, meanb);                           // 8
    sage_gemm_mma<false><<<UB + IB, 256, GEMM_SMEM>>>(meanb,
        u1, i1,
        w2_iu_l, w2_iu_r, w2_ui_l, w2_ui_r,
        b2_iu, b2_ui, u2, i2);                                      // 9

    // ---- classifier ----
    classify_kernel<<<(EL_N + 7) / 8, 256>>>(u2, i2, lbl, out);     // 10
}